// round 8
// baseline (speedup 1.0000x reference)
#include <cuda_runtime.h>
#include <cuda_bf16.h>
#include <cstdint>

#define MARGIN 0.5f
#define EPSV   1e-5f

#define N_MAX  8192
#define D_MAX  256
#define TM 128
#define TN 128

#if defined(__CUDA_ARCH__) && (__CUDA_ARCH__ == 1030) && defined(__CUDA_ARCH_FEAT_SM103_ALL)
#define HAS_TCGEN05 1
#else
#define HAS_TCGEN05 0
#endif

// ---------------------------------------------------------------------------
// Device scratch
// ---------------------------------------------------------------------------
__device__ float          g_pos[N_MAX];
__device__ float          g_neg[N_MAX];
__device__ int            g_targ[N_MAX];
__device__ __nv_bfloat16  g_featbf[N_MAX * D_MAX];
__device__ int            g_done;

// ---------------------------------------------------------------------------
// Prep: fp32->bf16 features, target->int32 (inline int64/int32 probe),
// zero accumulators + ticket.
// ---------------------------------------------------------------------------
__global__ void convert_kernel(const float* __restrict__ feat,
                               const void* __restrict__ targ, int n, int d) {
    __shared__ int s_is64;
    const int i = blockIdx.x * blockDim.x + threadIdx.x;

    const bool need_t = (blockIdx.x * blockDim.x) < n;
    if (need_t) {
        if (threadIdx.x == 0) {
            const long long* t = (const long long*)targ;
            int m = n / 2; if (m > 33) m = 33;
            bool is64 = true;
            for (int k = 1; k < m; ++k) {
                long long v = t[k];
                if (v < 0 || v >= (1LL << 30)) { is64 = false; break; }
            }
            s_is64 = is64 ? 1 : 0;
        }
        __syncthreads();
    }

    const int total4 = (n * d) >> 2;
    if (i < total4) {
        float4 v = reinterpret_cast<const float4*>(feat)[i];
        __nv_bfloat162 lo = __nv_bfloat162(__float2bfloat16(v.x), __float2bfloat16(v.y));
        __nv_bfloat162 hi = __nv_bfloat162(__float2bfloat16(v.z), __float2bfloat16(v.w));
        reinterpret_cast<__nv_bfloat162*>(g_featbf)[i * 2 + 0] = lo;
        reinterpret_cast<__nv_bfloat162*>(g_featbf)[i * 2 + 1] = hi;
    }
    if (i < n) {
        g_pos[i] = 0.0f; g_neg[i] = 0.0f;
        g_targ[i] = s_is64 ? (int)((const long long*)targ)[i]
                           : ((const int*)targ)[i];
    }
    if (i == 0) g_done = 0;
}

// ---------------------------------------------------------------------------
// PTX helpers
// ---------------------------------------------------------------------------
__device__ __forceinline__ uint32_t smem_u32(const void* p) {
    uint32_t a;
    asm("{ .reg .u64 t; cvta.to.shared.u64 t, %1; cvt.u32.u64 %0, t; }"
        : "=r"(a) : "l"(p));
    return a;
}

__device__ __forceinline__ uint32_t elect_one() {
    uint32_t pred;
    asm volatile("{\n\t.reg .pred p;\n\telect.sync _|p, 0xFFFFFFFF;\n\t"
                 "selp.b32 %0, 1, 0, p;\n\t}" : "=r"(pred));
    return pred;
}

#define MBARRIER_INIT(mbar, count) \
    asm volatile("mbarrier.init.shared.b64 [%0], %1;" \
                 :: "r"((uint32_t)(mbar)), "r"((uint32_t)(count)) : "memory")

#define MBARRIER_WAIT_PARITY(mbar, parity) do {                                   \
    uint32_t _m = (uint32_t)(mbar); uint32_t _p = (uint32_t)(parity);             \
    uint32_t _done;                                                               \
    asm volatile("{\n\t.reg .pred p;\n\t"                                         \
        "mbarrier.try_wait.parity.acquire.cta.shared::cta.b64 p, [%1], %2;\n\t"   \
        "selp.b32 %0, 1, 0, p;\n\t}" : "=r"(_done) : "r"(_m), "r"(_p) : "memory");\
    if (!_done) {                                                                 \
        asm volatile("{\n\t.reg .pred P1;\n\t"                                    \
            "WAIT_LOOP_%=:\n\t"                                                   \
            "mbarrier.try_wait.parity.acquire.cta.shared::cta.b64 P1, [%0], %1, 0x989680;\n\t" \
            "@P1 bra.uni WAIT_DONE_%=;\n\t"                                       \
            "bra.uni WAIT_LOOP_%=;\n\t"                                           \
            "WAIT_DONE_%=:\n\t}" :: "r"(_m), "r"(_p) : "memory");                 \
    }                                                                             \
} while (0)

#if HAS_TCGEN05

#define TCGEN05_ALLOC(sm_addr, nCols) \
    asm volatile("tcgen05.alloc.cta_group::1.sync.aligned.shared::cta.b32 [%0], %1;" \
                 :: "r"((uint32_t)(sm_addr)), "r"((uint32_t)(nCols)) : "memory")
#define TCGEN05_DEALLOC(tmem_addr, nCols) \
    asm volatile("tcgen05.dealloc.cta_group::1.sync.aligned.b32 %0, %1;" \
                 :: "r"(tmem_addr), "r"((uint32_t)(nCols)))
#define TCGEN05_RELINQUISH() \
    asm volatile("tcgen05.relinquish_alloc_permit.cta_group::1.sync.aligned;")
#define TCGEN05_COMMIT(mbar) \
    asm volatile("tcgen05.commit.cta_group::1.mbarrier::arrive::one.shared::cluster.b64 [%0];" \
                 :: "r"((uint32_t)(mbar)) : "memory")
#define TCGEN05_FENCE_AFTER()  asm volatile("tcgen05.fence::after_thread_sync;"  ::: "memory")
#define TCGEN05_FENCE_BEFORE() asm volatile("tcgen05.fence::before_thread_sync;" ::: "memory")
#define TCGEN05_WAIT_LD()      asm volatile("tcgen05.wait::ld.sync.aligned;"     ::: "memory")

#define TCGEN05_LD_32X32B_X32(r, tmem_addr) \
    asm volatile( \
        "tcgen05.ld.sync.aligned.32x32b.x32.b32 " \
        "{%0, %1, %2, %3, %4, %5, %6, %7, " \
        " %8, %9, %10, %11, %12, %13, %14, %15, " \
        " %16, %17, %18, %19, %20, %21, %22, %23, " \
        " %24, %25, %26, %27, %28, %29, %30, %31}, [%32];" \
        : "=r"((r)[0]),  "=r"((r)[1]),  "=r"((r)[2]),  "=r"((r)[3]), \
          "=r"((r)[4]),  "=r"((r)[5]),  "=r"((r)[6]),  "=r"((r)[7]), \
          "=r"((r)[8]),  "=r"((r)[9]),  "=r"((r)[10]), "=r"((r)[11]), \
          "=r"((r)[12]), "=r"((r)[13]), "=r"((r)[14]), "=r"((r)[15]), \
          "=r"((r)[16]), "=r"((r)[17]), "=r"((r)[18]), "=r"((r)[19]), \
          "=r"((r)[20]), "=r"((r)[21]), "=r"((r)[22]), "=r"((r)[23]), \
          "=r"((r)[24]), "=r"((r)[25]), "=r"((r)[26]), "=r"((r)[27]), \
          "=r"((r)[28]), "=r"((r)[29]), "=r"((r)[30]), "=r"((r)[31]) \
        : "r"(tmem_addr))

// SW128 K-major descriptor: version=1, SBO=64, LBO=1
static constexpr uint64_t SMEM_DESC_BASE_SW128 =
    (uint64_t(2)  << 61) | (uint64_t(1) << 46) | (uint64_t(64) << 32) | (uint64_t(1) << 16);

__device__ __forceinline__ uint64_t make_desc(uint32_t addr) {
    return SMEM_DESC_BASE_SW128 | ((uint64_t)(addr >> 4) & 0x3FFF);
}

__device__ __forceinline__ void mma_f16_ss(uint32_t d_tmem, uint64_t a_desc,
                                           uint64_t b_desc, uint32_t idesc, bool acc) {
    uint32_t en = acc ? 1u : 0u;
    asm volatile(
        "{\n\t.reg .pred p;\n\tsetp.ne.u32 p, %5, 0;\n\t"
        "tcgen05.mma.cta_group::1.kind::f16 [%0], %1, %2, %3, {%4, %4, %4, %4}, p;\n\t}"
        :: "r"(d_tmem), "l"(a_desc), "l"(b_desc), "r"(idesc), "r"(0u), "r"(en)
        : "memory");
}

// fp32 acc, bf16 a/b, M=128, N=128
static constexpr uint32_t MMA_IDESC =
    (1u << 4) | (1u << 7) | (1u << 10) | ((TN / 8) << 17) | ((TM / 16) << 24);

#endif  // HAS_TCGEN05

// ---------------------------------------------------------------------------
// SMEM layout
// ---------------------------------------------------------------------------
#define SMEM_A        0
#define SMEM_B0       65536
#define SMEM_B1       131072
#define SMEM_TCOL0    196608
#define SMEM_TCOL1    197120
#define SMEM_MBAR0    197632
#define SMEM_MBAR1    197640
#define SMEM_TMEMPTR  197648
#define SMEM_TOTAL    197664

#define TMEM_COLS     256   // two 128-col fp32 D buffers
#define GRID_CTAS     148
#define NTHREADS      512

#if HAS_TCGEN05
// Load one 128-row bf16 tile into SW128 K-major blocked-atom layout at `dst`.
template <int NT>
__device__ __forceinline__ void load_tile(char* smem, uint32_t dst,
                                          int gbase, int d8, int tid) {
    const uint4* src = reinterpret_cast<const uint4*>(g_featbf);
    if (d8 == 32) {
        #pragma unroll
        for (int k = 0; k < 4096 / NT; ++k) {
            int idx = tid + k * NT;
            int r = idx >> 5, ch = idx & 31;
            uint32_t byte = ((uint32_t)((r >> 3) + (ch >> 3) * 16) << 10)
                          + ((uint32_t)(r & 7) << 7) + ((uint32_t)(ch & 7) << 4);
            uint32_t sw = byte ^ ((byte >> 3) & 0x70);
            *reinterpret_cast<uint4*>(smem + dst + sw) =
                src[(size_t)(gbase + r) * 32 + ch];
        }
    } else {
        int chunks = TM * d8;
        for (int idx = tid; idx < chunks; idx += NT) {
            int r = idx / d8, ch = idx - r * d8;
            uint32_t byte = ((uint32_t)((r >> 3) + (ch >> 3) * 16) << 10)
                          + ((uint32_t)(r & 7) << 7) + ((uint32_t)(ch & 7) << 4);
            uint32_t sw = byte ^ ((byte >> 3) & 0x70);
            *reinterpret_cast<uint4*>(smem + dst + sw) =
                src[(size_t)(gbase + r) * (size_t)d8 + ch];
        }
    }
}

__device__ __forceinline__ void issue_mma_batch(uint32_t d_tmem, uint32_t a_addr,
                                                uint32_t b_addr, int nk,
                                                uint32_t mbar) {
    uint64_t a_base = make_desc(a_addr);
    uint64_t b_base = make_desc(b_addr);
    for (int s = 0; s < nk; ++s) {
        uint64_t off = ((uint64_t)(s >> 2) << 10) | (uint64_t)((s & 3) << 1);
        mma_f16_ss(d_tmem, a_base + off, b_base + off, MMA_IDESC, s > 0);
    }
    TCGEN05_COMMIT(mbar);
}
#endif

// ---------------------------------------------------------------------------
// Persistent pipelined sim kernel — ALL 16 warps do load + epilogue.
// Iteration: prefetch B(t+1) -> sync -> issue MMA(t+1) -> wait mbar(t),
// BRANCH-FREE epilogue(t) (32 elems/thread, pure selects) -> sync.
// Epilogue map: warp w -> rows (w&3)*32+lane, cols (w>>2)*32 .. +31.
// ---------------------------------------------------------------------------
__global__ __launch_bounds__(NTHREADS, 1)
void sim_tc_kernel(float* out, int n, int d, int n_new, float alpha)
{
#if HAS_TCGEN05
    extern __shared__ __align__(1024) char smem[];
    const uint32_t sb = smem_u32(smem);
    const int tid  = threadIdx.x;
    const int wid  = tid >> 5;
    const int lane = tid & 31;

    if (wid == 0) {
        TCGEN05_ALLOC(sb + SMEM_TMEMPTR, TMEM_COLS);
        TCGEN05_RELINQUISH();
    }
    if (tid == 0) {
        MBARRIER_INIT(sb + SMEM_MBAR0, 1);
        MBARRIER_INIT(sb + SMEM_MBAR1, 1);
    }
    __syncthreads();

    uint32_t tmem;
    asm volatile("ld.shared.b32 %0, [%1];" : "=r"(tmem) : "r"(sb + SMEM_TMEMPTR));

    // ---- tile enumeration ---------------------------------------------------
    const int slabs_new = n_new / TM;
    const int cols_full = n / TN;
    const int cols_new  = n_new / TN;
    const int slabs_tot = n / TM;
    const int tiles_new = slabs_new * cols_full;
    const int tiles_tot = tiles_new + (slabs_tot - slabs_new) * cols_new;

    const int G = gridDim.x;
    int t   = (int)((long long)blockIdx.x       * tiles_tot / G);
    int end = (int)((long long)(blockIdx.x + 1) * tiles_tot / G);

    const int d8 = d >> 3;
    const int nk = d >> 4;
    const int row  = (wid & 3) * 32 + lane;      // row in slab (subpartition)
    const int cblk = (wid >> 2) * 32;            // 32-col block for epilogue

    int c = 0;                                   // global tile counter (parity)

    while (t < end) {
        // decode run: contiguous tiles sharing one row slab
        int slab, col0, slab_cols, slab_t0;
        if (t < tiles_new) {
            slab = t / cols_full; col0 = t - slab * cols_full;
            slab_cols = cols_full; slab_t0 = slab * cols_full;
        } else {
            int u = t - tiles_new;
            slab = slabs_new + u / cols_new; col0 = u % cols_new;
            slab_cols = cols_new;
            slab_t0 = tiles_new + (slab - slabs_new) * cols_new;
        }
        int run_len = slab_t0 + slab_cols - t;
        if (run_len > end - t) run_len = end - t;
        const int rowbase = slab * TM;
        const bool row_new = rowbase < n_new;

        // ---- run prologue: A + B(0) + tcol(0), issue MMA(0) -----------------
        load_tile<NTHREADS>(smem, SMEM_A, rowbase, d8, tid);
        {
            int colbase = col0 * TN;
            load_tile<NTHREADS>(smem, (c & 1) ? SMEM_B1 : SMEM_B0, colbase, d8, tid);
            if (tid < TN)
                ((int*)(smem + ((c & 1) ? SMEM_TCOL1 : SMEM_TCOL0)))[tid] =
                    g_targ[colbase + tid];
        }
        asm volatile("fence.proxy.async.shared::cta;" ::: "memory");
        __syncthreads();
        if (wid == 0 && elect_one()) {
            issue_mma_batch(tmem + (c & 1) * 128, sb + SMEM_A,
                            sb + ((c & 1) ? SMEM_B1 : SMEM_B0), nk,
                            sb + ((c & 1) ? SMEM_MBAR1 : SMEM_MBAR0));
        }

        const int ti = __ldg(&g_targ[rowbase + row]);
        float p = 0.0f, ng = 0.0f;

        // ---- pipelined loop (MMA one tile ahead) -----------------------------
        for (int i = 0; i < run_len; ++i) {
            const int cc = c + i;
            const bool has_next = (i + 1 < run_len);

            // (A) prefetch B(t+1)+tcol(t+1) — independent of MMA(t)
            if (has_next) {
                int colbase = (col0 + i + 1) * TN;
                load_tile<NTHREADS>(smem, ((cc + 1) & 1) ? SMEM_B1 : SMEM_B0,
                                    colbase, d8, tid);
                if (tid < TN)
                    ((int*)(smem + (((cc + 1) & 1) ? SMEM_TCOL1
                                                   : SMEM_TCOL0)))[tid] =
                        g_targ[colbase + tid];
                asm volatile("fence.proxy.async.shared::cta;" ::: "memory");
            }
            // (B) B(t+1) visible to async proxy; everyone past epilogue(t-1)
            __syncthreads();

            // (C) issue MMA(t+1) — D(t+1) buffer consumed in iter i-1
            if (has_next && wid == 0 && elect_one()) {
                issue_mma_batch(tmem + ((cc + 1) & 1) * 128, sb + SMEM_A,
                                sb + (((cc + 1) & 1) ? SMEM_B1 : SMEM_B0), nk,
                                sb + (((cc + 1) & 1) ? SMEM_MBAR1 : SMEM_MBAR0));
            }

            // (D) epilogue(t): wait, LDTM, BRANCH-FREE mask math
            {
                MBARRIER_WAIT_PARITY(sb + ((cc & 1) ? SMEM_MBAR1 : SMEM_MBAR0),
                                     (cc >> 1) & 1);
                TCGEN05_FENCE_AFTER();

                const int colbase = (col0 + i) * TN;
                const bool do_pos = row_new && (colbase < n_new);
                const uint32_t tc_base = sb + ((cc & 1) ? SMEM_TCOL1
                                                        : SMEM_TCOL0) + cblk * 4;
                // hoist the 32 column targets into registers (8 x LDS.128,
                // lane-uniform addresses -> broadcast, conflict-free)
                int tcr[32];
                #pragma unroll
                for (int v = 0; v < 8; ++v) {
                    asm volatile("ld.shared.v4.b32 {%0,%1,%2,%3}, [%4];"
                        : "=r"(tcr[v*4+0]), "=r"(tcr[v*4+1]),
                          "=r"(tcr[v*4+2]), "=r"(tcr[v*4+3])
                        : "r"(tc_base + v * 16));
                }

                uint32_t dr[32];
                TCGEN05_LD_32X32B_X32(dr, tmem + (cc & 1) * 128 + cblk);
                TCGEN05_WAIT_LD();

                if (do_pos) {
                    #pragma unroll
                    for (int j = 0; j < 32; ++j) {
                        const float s   = __uint_as_float(dr[j]);
                        const bool diff = (ti != tcr[j]);
                        const float cn  = (s > MARGIN) ? s : 0.0f;
                        const float cp  = (s < 1.0f - EPSV) ? (1.0f - s) : 0.0f;
                        ng += diff ? cn : 0.0f;
                        p  += diff ? 0.0f : cp;
                    }
                } else {
                    #pragma unroll
                    for (int j = 0; j < 32; ++j) {
                        const float s   = __uint_as_float(dr[j]);
                        const bool take = (ti != tcr[j]) & (s > MARGIN);
                        ng += take ? s : 0.0f;
                    }
                }
                TCGEN05_FENCE_BEFORE();
            }

            // (E) end-of-iter: D(t)/tcol(t) consumed before next overwrite
            __syncthreads();
        }

        // ---- run epilogue: flush accumulators (4 threads per row) -----------
        atomicAdd(&g_neg[rowbase + row], ng);
        if (p != 0.0f) atomicAdd(&g_pos[rowbase + row], p);

        c += run_len;
        t += run_len;
    }

    __syncthreads();
    if (wid == 0) TCGEN05_DEALLOC(tmem, TMEM_COLS);

    // ---- last CTA computes the final scalar ---------------------------------
    __threadfence();
    __shared__ int s_last;
    if (tid == 0)
        s_last = (atomicAdd(&g_done, 1) == gridDim.x - 1) ? 1 : 0;
    __syncthreads();
    if (s_last) {
        double* sh = reinterpret_cast<double*>(smem);
        const double a = (double)alpha;
        const double b = 1.0 - a;
        const double stale = (double)__ldcg(&g_pos[n_new - 1]);
        double s = 0.0;
        for (int i = tid; i < n; i += NTHREADS) {
            double pv = (i < n_new) ? (double)__ldcg(&g_pos[i]) : stale;
            s += a * pv + b * (double)__ldcg(&g_neg[i]);
        }
        sh[tid] = s;
        __syncthreads();
        for (int off = NTHREADS / 2; off > 0; off >>= 1) {
            if (tid < off) sh[tid] += sh[tid + off];
            __syncthreads();
        }
        if (tid == 0) out[0] = (float)(sh[0] / (double)n);
    }
#endif  // HAS_TCGEN05
}

// ---------------------------------------------------------------------------
extern "C" void kernel_launch(void* const* d_in, const int* in_sizes, int n_in,
                              void* d_out, int out_size)
{
    const float* feat = (const float*)d_in[0];
    const void*  targ = d_in[1];

    const int n     = in_sizes[1];             // 8192
    const int d     = in_sizes[0] / n;         // 256
    const int n_new = in_sizes[2];             // 4096
    const int n_old = (n_in > 3) ? in_sizes[3] : 0;
    const float alpha = (n_old != 0) ? 0.9f : 0.5f;

    cudaFuncSetAttribute(sim_tc_kernel,
                         cudaFuncAttributeMaxDynamicSharedMemorySize, SMEM_TOTAL);

    {
        int total4 = (n * d) >> 2;
        convert_kernel<<<(total4 + 255) / 256, 256>>>(feat, targ, n, d);
    }
    sim_tc_kernel<<<GRID_CTAS, NTHREADS, SMEM_TOTAL>>>((float*)d_out, n, d, n_new, alpha);
}

// round 9
// speedup vs baseline: 1.1595x; 1.1595x over previous
#include <cuda_runtime.h>
#include <cuda_bf16.h>
#include <cstdint>

#define MARGIN 0.5f
#define EPSV   1e-5f

#define N_MAX  8192
#define D_MAX  256
#define TM 128
#define TN 128

#if defined(__CUDA_ARCH__) && (__CUDA_ARCH__ == 1030) && defined(__CUDA_ARCH_FEAT_SM103_ALL)
#define HAS_TCGEN05 1
#else
#define HAS_TCGEN05 0
#endif

// ---------------------------------------------------------------------------
// Device scratch
// ---------------------------------------------------------------------------
__device__ float          g_pos[N_MAX];
__device__ float          g_neg[N_MAX];
__device__ int            g_targ[N_MAX];
__device__ __nv_bfloat16  g_featbf[N_MAX * D_MAX];
__device__ int            g_done;

// ---------------------------------------------------------------------------
// Prep: fp32->bf16 features, target->int32 (inline int64/int32 probe),
// zero accumulators + ticket.
// ---------------------------------------------------------------------------
__global__ void convert_kernel(const float* __restrict__ feat,
                               const void* __restrict__ targ, int n, int d) {
    __shared__ int s_is64;
    const int i = blockIdx.x * blockDim.x + threadIdx.x;

    const bool need_t = (blockIdx.x * blockDim.x) < n;
    if (need_t) {
        if (threadIdx.x == 0) {
            const long long* t = (const long long*)targ;
            int m = n / 2; if (m > 33) m = 33;
            bool is64 = true;
            for (int k = 1; k < m; ++k) {
                long long v = t[k];
                if (v < 0 || v >= (1LL << 30)) { is64 = false; break; }
            }
            s_is64 = is64 ? 1 : 0;
        }
        __syncthreads();
    }

    const int total4 = (n * d) >> 2;
    if (i < total4) {
        float4 v = reinterpret_cast<const float4*>(feat)[i];
        __nv_bfloat162 lo = __nv_bfloat162(__float2bfloat16(v.x), __float2bfloat16(v.y));
        __nv_bfloat162 hi = __nv_bfloat162(__float2bfloat16(v.z), __float2bfloat16(v.w));
        reinterpret_cast<__nv_bfloat162*>(g_featbf)[i * 2 + 0] = lo;
        reinterpret_cast<__nv_bfloat162*>(g_featbf)[i * 2 + 1] = hi;
    }
    if (i < n) {
        g_pos[i] = 0.0f; g_neg[i] = 0.0f;
        g_targ[i] = s_is64 ? (int)((const long long*)targ)[i]
                           : ((const int*)targ)[i];
    }
    if (i == 0) g_done = 0;
}

// ---------------------------------------------------------------------------
// PTX helpers
// ---------------------------------------------------------------------------
__device__ __forceinline__ uint32_t smem_u32(const void* p) {
    uint32_t a;
    asm("{ .reg .u64 t; cvta.to.shared.u64 t, %1; cvt.u32.u64 %0, t; }"
        : "=r"(a) : "l"(p));
    return a;
}

__device__ __forceinline__ uint32_t elect_one() {
    uint32_t pred;
    asm volatile("{\n\t.reg .pred p;\n\telect.sync _|p, 0xFFFFFFFF;\n\t"
                 "selp.b32 %0, 1, 0, p;\n\t}" : "=r"(pred));
    return pred;
}

#define MBARRIER_INIT(mbar, count) \
    asm volatile("mbarrier.init.shared.b64 [%0], %1;" \
                 :: "r"((uint32_t)(mbar)), "r"((uint32_t)(count)) : "memory")

#define MBARRIER_WAIT_PARITY(mbar, parity) do {                                   \
    uint32_t _m = (uint32_t)(mbar); uint32_t _p = (uint32_t)(parity);             \
    uint32_t _done;                                                               \
    asm volatile("{\n\t.reg .pred p;\n\t"                                         \
        "mbarrier.try_wait.parity.acquire.cta.shared::cta.b64 p, [%1], %2;\n\t"   \
        "selp.b32 %0, 1, 0, p;\n\t}" : "=r"(_done) : "r"(_m), "r"(_p) : "memory");\
    if (!_done) {                                                                 \
        asm volatile("{\n\t.reg .pred P1;\n\t"                                    \
            "WAIT_LOOP_%=:\n\t"                                                   \
            "mbarrier.try_wait.parity.acquire.cta.shared::cta.b64 P1, [%0], %1, 0x989680;\n\t" \
            "@P1 bra.uni WAIT_DONE_%=;\n\t"                                       \
            "bra.uni WAIT_LOOP_%=;\n\t"                                           \
            "WAIT_DONE_%=:\n\t}" :: "r"(_m), "r"(_p) : "memory");                 \
    }                                                                             \
} while (0)

#if HAS_TCGEN05

#define TCGEN05_ALLOC(sm_addr, nCols) \
    asm volatile("tcgen05.alloc.cta_group::1.sync.aligned.shared::cta.b32 [%0], %1;" \
                 :: "r"((uint32_t)(sm_addr)), "r"((uint32_t)(nCols)) : "memory")
#define TCGEN05_DEALLOC(tmem_addr, nCols) \
    asm volatile("tcgen05.dealloc.cta_group::1.sync.aligned.b32 %0, %1;" \
                 :: "r"(tmem_addr), "r"((uint32_t)(nCols)))
#define TCGEN05_RELINQUISH() \
    asm volatile("tcgen05.relinquish_alloc_permit.cta_group::1.sync.aligned;")
#define TCGEN05_COMMIT(mbar) \
    asm volatile("tcgen05.commit.cta_group::1.mbarrier::arrive::one.shared::cluster.b64 [%0];" \
                 :: "r"((uint32_t)(mbar)) : "memory")
#define TCGEN05_FENCE_AFTER()  asm volatile("tcgen05.fence::after_thread_sync;"  ::: "memory")
#define TCGEN05_FENCE_BEFORE() asm volatile("tcgen05.fence::before_thread_sync;" ::: "memory")
#define TCGEN05_WAIT_LD()      asm volatile("tcgen05.wait::ld.sync.aligned;"     ::: "memory")
#define TCGEN05_WAIT_ST()      asm volatile("tcgen05.wait::st.sync.aligned;"     ::: "memory")

#define TCGEN05_LD_32X32B_X32(r, tmem_addr) \
    asm volatile( \
        "tcgen05.ld.sync.aligned.32x32b.x32.b32 " \
        "{%0, %1, %2, %3, %4, %5, %6, %7, " \
        " %8, %9, %10, %11, %12, %13, %14, %15, " \
        " %16, %17, %18, %19, %20, %21, %22, %23, " \
        " %24, %25, %26, %27, %28, %29, %30, %31}, [%32];" \
        : "=r"((r)[0]),  "=r"((r)[1]),  "=r"((r)[2]),  "=r"((r)[3]), \
          "=r"((r)[4]),  "=r"((r)[5]),  "=r"((r)[6]),  "=r"((r)[7]), \
          "=r"((r)[8]),  "=r"((r)[9]),  "=r"((r)[10]), "=r"((r)[11]), \
          "=r"((r)[12]), "=r"((r)[13]), "=r"((r)[14]), "=r"((r)[15]), \
          "=r"((r)[16]), "=r"((r)[17]), "=r"((r)[18]), "=r"((r)[19]), \
          "=r"((r)[20]), "=r"((r)[21]), "=r"((r)[22]), "=r"((r)[23]), \
          "=r"((r)[24]), "=r"((r)[25]), "=r"((r)[26]), "=r"((r)[27]), \
          "=r"((r)[28]), "=r"((r)[29]), "=r"((r)[30]), "=r"((r)[31]) \
        : "r"(tmem_addr))

#define TCGEN05_ST_32X32B_X32(tmem_addr, r) \
    asm volatile( \
        "tcgen05.st.sync.aligned.32x32b.x32.b32 [%0], " \
        "{%1, %2, %3, %4, %5, %6, %7, %8, " \
        " %9, %10, %11, %12, %13, %14, %15, %16, " \
        " %17, %18, %19, %20, %21, %22, %23, %24, " \
        " %25, %26, %27, %28, %29, %30, %31, %32};" \
        :: "r"(tmem_addr), \
           "r"((r)[0]),  "r"((r)[1]),  "r"((r)[2]),  "r"((r)[3]), \
           "r"((r)[4]),  "r"((r)[5]),  "r"((r)[6]),  "r"((r)[7]), \
           "r"((r)[8]),  "r"((r)[9]),  "r"((r)[10]), "r"((r)[11]), \
           "r"((r)[12]), "r"((r)[13]), "r"((r)[14]), "r"((r)[15]), \
           "r"((r)[16]), "r"((r)[17]), "r"((r)[18]), "r"((r)[19]), \
           "r"((r)[20]), "r"((r)[21]), "r"((r)[22]), "r"((r)[23]), \
           "r"((r)[24]), "r"((r)[25]), "r"((r)[26]), "r"((r)[27]), \
           "r"((r)[28]), "r"((r)[29]), "r"((r)[30]), "r"((r)[31]) \
        : "memory")

// SW128 K-major descriptor: version=1, SBO=64, LBO=1
static constexpr uint64_t SMEM_DESC_BASE_SW128 =
    (uint64_t(2)  << 61) | (uint64_t(1) << 46) | (uint64_t(64) << 32) | (uint64_t(1) << 16);

__device__ __forceinline__ uint64_t make_desc(uint32_t addr) {
    return SMEM_DESC_BASE_SW128 | ((uint64_t)(addr >> 4) & 0x3FFF);
}

// TS-mode bf16 MMA: A in TMEM, B in SMEM (pattern from test_mma.cu)
__device__ __forceinline__ void mma_f16_ts(uint32_t d_tmem, uint32_t a_tmem,
                                           uint64_t b_desc, uint32_t idesc, bool acc) {
    uint32_t en = acc ? 1u : 0u;
    asm volatile(
        "{\n\t.reg .pred p;\n\tsetp.ne.u32 p, %5, 0;\n\t"
        "tcgen05.mma.cta_group::1.kind::f16 [%0], [%1], %2, %3, {%4, %4, %4, %4}, p;\n\t}"
        :: "r"(d_tmem), "r"(a_tmem), "l"(b_desc), "r"(idesc), "r"(0u), "r"(en)
        : "memory");
}

// fp32 acc, bf16 a/b, M=128, N=128
static constexpr uint32_t MMA_IDESC =
    (1u << 4) | (1u << 7) | (1u << 10) | ((TN / 8) << 17) | ((TM / 16) << 24);

#endif  // HAS_TCGEN05

// ---------------------------------------------------------------------------
// SMEM layout: 3 B buffers (A lives in TMEM)
// ---------------------------------------------------------------------------
#define SMEM_B(b)     ((b) * 65536)
#define SMEM_TCOL(b)  (196608 + (b) * 512)
#define SMEM_MBAR(b)  (198144 + (b) * 8)
#define SMEM_TMEMPTR  198168
#define SMEM_TOTAL    198176

#define TMEM_COLS     512   // 3 x 128 D buffers + 128 cols A
#define TMEM_D(b)     ((b) * 128)
#define TMEM_A_OFF    384

#define GRID_CTAS     148
#define NTHREADS      512

#if HAS_TCGEN05
// Load one 128-row bf16 tile (d=256) into SW128 K-major blocked-atom layout.
__device__ __forceinline__ void load_tile256(char* smem, uint32_t dst,
                                             int gbase, int tid) {
    const uint4* src = reinterpret_cast<const uint4*>(g_featbf);
    #pragma unroll
    for (int k = 0; k < 16; ++k) {
        int idx = tid + k * 256;
        int r = idx >> 5, ch = idx & 31;
        uint32_t byte = ((uint32_t)((r >> 3) + (ch >> 3) * 16) << 10)
                      + ((uint32_t)(r & 7) << 7) + ((uint32_t)(ch & 7) << 4);
        uint32_t sw = byte ^ ((byte >> 3) & 0x70);
        *reinterpret_cast<uint4*>(smem + dst + sw) =
            src[(size_t)(gbase + r) * 32 + ch];
    }
}
// Same, arbitrary thread count (prologue: 384 threads)
__device__ __forceinline__ void load_tile_any(char* smem, uint32_t dst,
                                              int gbase, int lt, int nt) {
    const uint4* src = reinterpret_cast<const uint4*>(g_featbf);
    for (int idx = lt; idx < 4096; idx += nt) {
        int r = idx >> 5, ch = idx & 31;
        uint32_t byte = ((uint32_t)((r >> 3) + (ch >> 3) * 16) << 10)
                      + ((uint32_t)(r & 7) << 7) + ((uint32_t)(ch & 7) << 4);
        uint32_t sw = byte ^ ((byte >> 3) & 0x70);
        *reinterpret_cast<uint4*>(smem + dst + sw) =
            src[(size_t)(gbase + r) * 32 + ch];
    }
}

// Issue one full-K (=256) MMA batch: 16 chained K=16 steps, TS mode.
__device__ __forceinline__ void issue_mma_ts(uint32_t d_tmem, uint32_t a_tmem,
                                             uint32_t b_addr, uint32_t mbar) {
    uint64_t b_base = make_desc(b_addr);
    #pragma unroll
    for (int s = 0; s < 16; ++s) {
        uint64_t boff = ((uint64_t)(s >> 2) << 10) | (uint64_t)((s & 3) << 1);
        mma_f16_ts(d_tmem, a_tmem + s * 8, b_base + boff, MMA_IDESC, s > 0);
    }
    TCGEN05_COMMIT(mbar);
}
#endif

// ---------------------------------------------------------------------------
// Persistent depth-3 pipelined sim kernel. A in TMEM (TS mode).
//   warps 0-7 : epilogue (D(t) via LDTM, branchy masks, 64 elems/thread)
//   warps 8-15: loaders (B(t+2)+tcol(t+2), then elect-issue MMA(t+2))
// MMA runs TWO tiles ahead -> its latency is never exposed to the epilogue.
// ---------------------------------------------------------------------------
__global__ __launch_bounds__(NTHREADS, 1)
void sim_tc_kernel(float* out, int n, int d, int n_new, float alpha)
{
#if HAS_TCGEN05
    extern __shared__ __align__(1024) char smem[];
    const uint32_t sb = smem_u32(smem);
    const int tid  = threadIdx.x;
    const int wid  = tid >> 5;
    const int lane = tid & 31;

    if (wid == 0) {
        TCGEN05_ALLOC(sb + SMEM_TMEMPTR, TMEM_COLS);
        TCGEN05_RELINQUISH();
    }
    if (tid == 0) {
        MBARRIER_INIT(sb + SMEM_MBAR(0), 1);
        MBARRIER_INIT(sb + SMEM_MBAR(1), 1);
        MBARRIER_INIT(sb + SMEM_MBAR(2), 1);
    }
    __syncthreads();

    uint32_t tmem;
    asm volatile("ld.shared.b32 %0, [%1];" : "=r"(tmem) : "r"(sb + SMEM_TMEMPTR));

    // ---- tile enumeration ---------------------------------------------------
    const int slabs_new = n_new / TM;
    const int cols_full = n / TN;
    const int cols_new  = n_new / TN;
    const int slabs_tot = n / TM;
    const int tiles_new = slabs_new * cols_full;
    const int tiles_tot = tiles_new + (slabs_tot - slabs_new) * cols_new;

    const int G = gridDim.x;
    int t   = (int)((long long)blockIdx.x       * tiles_tot / G);
    int end = (int)((long long)(blockIdx.x + 1) * tiles_tot / G);

    const bool is_loader = wid >= 8;
    const int  row  = (wid & 3) * 32 + lane;     // epilogue row (subpartition)
    const int  colh = (wid >> 2) & 1;            // epilogue col half

    int c = 0;                                   // global tile counter

    while (t < end) {
        // decode run: contiguous tiles sharing one row slab
        int slab, col0, slab_cols, slab_t0;
        if (t < tiles_new) {
            slab = t / cols_full; col0 = t - slab * cols_full;
            slab_cols = cols_full; slab_t0 = slab * cols_full;
        } else {
            int u = t - tiles_new;
            slab = slabs_new + u / cols_new; col0 = u % cols_new;
            slab_cols = cols_new;
            slab_t0 = tiles_new + (slab - slabs_new) * cols_new;
        }
        int run_len = slab_t0 + slab_cols - t;
        if (run_len > end - t) run_len = end - t;
        const int rowbase = slab * TM;
        const bool row_new = rowbase < n_new;
        const int kmax = run_len < 2 ? run_len : 2;

        // ---- run prologue ----------------------------------------------------
        // warps 0-3: A row slab -> TMEM (lane=row, bf16x2 packed along K)
        // warps 4-15 (384 thr): B(c..c+kmax-1) + tcols
        if (wid < 4) {
            const uint4* src = reinterpret_cast<const uint4*>(g_featbf);
            const uint32_t woff = (uint32_t)wid << 21;
            #pragma unroll
            for (int q = 0; q < 4; ++q) {
                uint32_t regs[32];
                #pragma unroll
                for (int j = 0; j < 8; ++j) {
                    uint4 v = src[(size_t)(rowbase + tid) * 32 + q * 8 + j];
                    regs[j * 4 + 0] = v.x; regs[j * 4 + 1] = v.y;
                    regs[j * 4 + 2] = v.z; regs[j * 4 + 3] = v.w;
                }
                TCGEN05_ST_32X32B_X32(tmem + TMEM_A_OFF + q * 32 + woff, regs);
            }
            TCGEN05_WAIT_ST();
            TCGEN05_FENCE_BEFORE();
        } else {
            const int lt = tid - 128;            // 0..383
            for (int k = 0; k < kmax; ++k) {
                const int b = (c + k) % 3;
                const int colbase = (col0 + k) * TN;
                load_tile_any(smem, SMEM_B(b), colbase, lt, 384);
                if (lt < TN)
                    ((int*)(smem + SMEM_TCOL(b)))[lt] = g_targ[colbase + lt];
            }
            asm volatile("fence.proxy.async.shared::cta;" ::: "memory");
        }
        __syncthreads();
        if (wid == 8 && elect_one()) {
            TCGEN05_FENCE_AFTER();
            for (int k = 0; k < kmax; ++k) {
                const int b = (c + k) % 3;
                issue_mma_ts(tmem + TMEM_D(b), tmem + TMEM_A_OFF,
                             sb + SMEM_B(b), sb + SMEM_MBAR(b));
            }
        }

        const int ti = __ldg(&g_targ[rowbase + row]);
        float p = 0.0f, ng = 0.0f;

        // ---- depth-3 pipelined loop -------------------------------------------
        for (int i = 0; i < run_len; ++i) {
            const int cc  = c + i;
            const int buf = cc % 3;

            if (is_loader) {
                if (i + 2 < run_len) {
                    const int cn = cc + 2;
                    const int bn = cn % 3;
                    const int colbase = (col0 + i + 2) * TN;
                    load_tile256(smem, SMEM_B(bn), colbase, tid - 256);
                    if (tid - 256 < TN)
                        ((int*)(smem + SMEM_TCOL(bn)))[tid - 256] =
                            g_targ[colbase + tid - 256];
                    asm volatile("fence.proxy.async.shared::cta;" ::: "memory");
                    asm volatile("bar.sync 2, 256;" ::: "memory");
                    if (wid == 8 && elect_one()) {
                        issue_mma_ts(tmem + TMEM_D(bn), tmem + TMEM_A_OFF,
                                     sb + SMEM_B(bn), sb + SMEM_MBAR(bn));
                    }
                }
            } else {
                // epilogue(t): mbar fired an iteration ago -> no stall
                MBARRIER_WAIT_PARITY(sb + SMEM_MBAR(buf), (cc / 3) & 1);
                TCGEN05_FENCE_AFTER();

                const int colbase = (col0 + i) * TN;
                const bool do_pos = row_new && (colbase < n_new);
                const int* tc = (const int*)(smem + SMEM_TCOL(buf)) + colh * 64;
                const uint32_t dbase = tmem + TMEM_D(buf) + colh * 64;
                uint32_t dr[32];
                if (do_pos) {
                    #pragma unroll
                    for (int q = 0; q < 2; ++q) {
                        TCGEN05_LD_32X32B_X32(dr, dbase + q * 32);
                        TCGEN05_WAIT_LD();
                        #pragma unroll
                        for (int j = 0; j < 32; ++j) {
                            const float s = __uint_as_float(dr[j]);
                            const int tj = tc[q * 32 + j];
                            if (ti != tj) {
                                if (s > MARGIN) ng += s;
                            } else if (s < 1.0f - EPSV) {
                                p += 1.0f - s;
                            }
                        }
                    }
                } else {
                    #pragma unroll
                    for (int q = 0; q < 2; ++q) {
                        TCGEN05_LD_32X32B_X32(dr, dbase + q * 32);
                        TCGEN05_WAIT_LD();
                        #pragma unroll
                        for (int j = 0; j < 32; ++j) {
                            const float s = __uint_as_float(dr[j]);
                            if (ti != tc[q * 32 + j] && s > MARGIN) ng += s;
                        }
                    }
                }
                TCGEN05_FENCE_BEFORE();
            }

            __syncthreads();   // tile cc fully consumed; buffers may rotate
        }

        // ---- run epilogue: flush accumulators (2 threads per row) -------------
        if (!is_loader) {
            atomicAdd(&g_neg[rowbase + row], ng);
            if (p != 0.0f) atomicAdd(&g_pos[rowbase + row], p);
        }

        c += run_len;
        t += run_len;
    }

    __syncthreads();
    if (wid == 0) TCGEN05_DEALLOC(tmem, TMEM_COLS);

    // ---- last CTA computes the final scalar ---------------------------------
    __threadfence();
    __shared__ int s_last;
    if (tid == 0)
        s_last = (atomicAdd(&g_done, 1) == gridDim.x - 1) ? 1 : 0;
    __syncthreads();
    if (s_last) {
        double* sh = reinterpret_cast<double*>(smem);
        const double a = (double)alpha;
        const double b = 1.0 - a;
        const double stale = (double)__ldcg(&g_pos[n_new - 1]);
        double s = 0.0;
        for (int i = tid; i < n; i += NTHREADS) {
            double pv = (i < n_new) ? (double)__ldcg(&g_pos[i]) : stale;
            s += a * pv + b * (double)__ldcg(&g_neg[i]);
        }
        sh[tid] = s;
        __syncthreads();
        for (int off = NTHREADS / 2; off > 0; off >>= 1) {
            if (tid < off) sh[tid] += sh[tid + off];
            __syncthreads();
        }
        if (tid == 0) out[0] = (float)(sh[0] / (double)n);
    }
#endif  // HAS_TCGEN05
}

// ---------------------------------------------------------------------------
extern "C" void kernel_launch(void* const* d_in, const int* in_sizes, int n_in,
                              void* d_out, int out_size)
{
    const float* feat = (const float*)d_in[0];
    const void*  targ = d_in[1];

    const int n     = in_sizes[1];             // 8192
    const int d     = in_sizes[0] / n;         // 256
    const int n_new = in_sizes[2];             // 4096
    const int n_old = (n_in > 3) ? in_sizes[3] : 0;
    const float alpha = (n_old != 0) ? 0.9f : 0.5f;

    cudaFuncSetAttribute(sim_tc_kernel,
                         cudaFuncAttributeMaxDynamicSharedMemorySize, SMEM_TOTAL);

    {
        int total4 = (n * d) >> 2;
        convert_kernel<<<(total4 + 255) / 256, 256>>>(feat, targ, n, d);
    }
    sim_tc_kernel<<<GRID_CTAS, NTHREADS, SMEM_TOTAL>>>((float*)d_out, n, d, n_new, alpha);
}

// round 10
// speedup vs baseline: 1.2723x; 1.0973x over previous
#include <cuda_runtime.h>
#include <cuda_bf16.h>
#include <cstdint>

#define MARGIN 0.5f
#define EPSV   1e-5f

#define N_MAX  8192
#define D_MAX  256
#define TM 128
#define TN 64

#if defined(__CUDA_ARCH__) && (__CUDA_ARCH__ == 1030) && defined(__CUDA_ARCH_FEAT_SM103_ALL)
#define HAS_TCGEN05 1
#else
#define HAS_TCGEN05 0
#endif

// ---------------------------------------------------------------------------
// Device scratch
// ---------------------------------------------------------------------------
__device__ float          g_pos[N_MAX];
__device__ float          g_neg[N_MAX];
__device__ int            g_targ[N_MAX];
__device__ __nv_bfloat16  g_featbf[N_MAX * D_MAX];
__device__ int            g_done;

// ---------------------------------------------------------------------------
// Prep: fp32->bf16 features, target->int32 (inline int64/int32 probe),
// zero accumulators + ticket.
// ---------------------------------------------------------------------------
__global__ void convert_kernel(const float* __restrict__ feat,
                               const void* __restrict__ targ, int n, int d) {
    __shared__ int s_is64;
    const int i = blockIdx.x * blockDim.x + threadIdx.x;

    const bool need_t = (blockIdx.x * blockDim.x) < n;
    if (need_t) {
        if (threadIdx.x == 0) {
            const long long* t = (const long long*)targ;
            int m = n / 2; if (m > 33) m = 33;
            bool is64 = true;
            for (int k = 1; k < m; ++k) {
                long long v = t[k];
                if (v < 0 || v >= (1LL << 30)) { is64 = false; break; }
            }
            s_is64 = is64 ? 1 : 0;
        }
        __syncthreads();
    }

    const int total4 = (n * d) >> 2;
    if (i < total4) {
        float4 v = reinterpret_cast<const float4*>(feat)[i];
        __nv_bfloat162 lo = __nv_bfloat162(__float2bfloat16(v.x), __float2bfloat16(v.y));
        __nv_bfloat162 hi = __nv_bfloat162(__float2bfloat16(v.z), __float2bfloat16(v.w));
        reinterpret_cast<__nv_bfloat162*>(g_featbf)[i * 2 + 0] = lo;
        reinterpret_cast<__nv_bfloat162*>(g_featbf)[i * 2 + 1] = hi;
    }
    if (i < n) {
        g_pos[i] = 0.0f; g_neg[i] = 0.0f;
        g_targ[i] = s_is64 ? (int)((const long long*)targ)[i]
                           : ((const int*)targ)[i];
    }
    if (i == 0) g_done = 0;
}

// ---------------------------------------------------------------------------
// PTX helpers
// ---------------------------------------------------------------------------
__device__ __forceinline__ uint32_t smem_u32(const void* p) {
    uint32_t a;
    asm("{ .reg .u64 t; cvta.to.shared.u64 t, %1; cvt.u32.u64 %0, t; }"
        : "=r"(a) : "l"(p));
    return a;
}

__device__ __forceinline__ uint32_t elect_one() {
    uint32_t pred;
    asm volatile("{\n\t.reg .pred p;\n\telect.sync _|p, 0xFFFFFFFF;\n\t"
                 "selp.b32 %0, 1, 0, p;\n\t}" : "=r"(pred));
    return pred;
}

#define MBARRIER_INIT(mbar, count) \
    asm volatile("mbarrier.init.shared.b64 [%0], %1;" \
                 :: "r"((uint32_t)(mbar)), "r"((uint32_t)(count)) : "memory")

#define MBARRIER_WAIT_PARITY(mbar, parity) do {                                   \
    uint32_t _m = (uint32_t)(mbar); uint32_t _p = (uint32_t)(parity);             \
    uint32_t _done;                                                               \
    asm volatile("{\n\t.reg .pred p;\n\t"                                         \
        "mbarrier.try_wait.parity.acquire.cta.shared::cta.b64 p, [%1], %2;\n\t"   \
        "selp.b32 %0, 1, 0, p;\n\t}" : "=r"(_done) : "r"(_m), "r"(_p) : "memory");\
    if (!_done) {                                                                 \
        asm volatile("{\n\t.reg .pred P1;\n\t"                                    \
            "WAIT_LOOP_%=:\n\t"                                                   \
            "mbarrier.try_wait.parity.acquire.cta.shared::cta.b64 P1, [%0], %1, 0x989680;\n\t" \
            "@P1 bra.uni WAIT_DONE_%=;\n\t"                                       \
            "bra.uni WAIT_LOOP_%=;\n\t"                                           \
            "WAIT_DONE_%=:\n\t}" :: "r"(_m), "r"(_p) : "memory");                 \
    }                                                                             \
} while (0)

#if HAS_TCGEN05

#define TCGEN05_ALLOC(sm_addr, nCols) \
    asm volatile("tcgen05.alloc.cta_group::1.sync.aligned.shared::cta.b32 [%0], %1;" \
                 :: "r"((uint32_t)(sm_addr)), "r"((uint32_t)(nCols)) : "memory")
#define TCGEN05_DEALLOC(tmem_addr, nCols) \
    asm volatile("tcgen05.dealloc.cta_group::1.sync.aligned.b32 %0, %1;" \
                 :: "r"(tmem_addr), "r"((uint32_t)(nCols)))
#define TCGEN05_RELINQUISH() \
    asm volatile("tcgen05.relinquish_alloc_permit.cta_group::1.sync.aligned;")
#define TCGEN05_COMMIT(mbar) \
    asm volatile("tcgen05.commit.cta_group::1.mbarrier::arrive::one.shared::cluster.b64 [%0];" \
                 :: "r"((uint32_t)(mbar)) : "memory")
#define TCGEN05_FENCE_AFTER()  asm volatile("tcgen05.fence::after_thread_sync;"  ::: "memory")
#define TCGEN05_FENCE_BEFORE() asm volatile("tcgen05.fence::before_thread_sync;" ::: "memory")
#define TCGEN05_WAIT_LD()      asm volatile("tcgen05.wait::ld.sync.aligned;"     ::: "memory")
#define TCGEN05_WAIT_ST()      asm volatile("tcgen05.wait::st.sync.aligned;"     ::: "memory")

#define TCGEN05_LD_32X32B_X32(r, tmem_addr) \
    asm volatile( \
        "tcgen05.ld.sync.aligned.32x32b.x32.b32 " \
        "{%0, %1, %2, %3, %4, %5, %6, %7, " \
        " %8, %9, %10, %11, %12, %13, %14, %15, " \
        " %16, %17, %18, %19, %20, %21, %22, %23, " \
        " %24, %25, %26, %27, %28, %29, %30, %31}, [%32];" \
        : "=r"((r)[0]),  "=r"((r)[1]),  "=r"((r)[2]),  "=r"((r)[3]), \
          "=r"((r)[4]),  "=r"((r)[5]),  "=r"((r)[6]),  "=r"((r)[7]), \
          "=r"((r)[8]),  "=r"((r)[9]),  "=r"((r)[10]), "=r"((r)[11]), \
          "=r"((r)[12]), "=r"((r)[13]), "=r"((r)[14]), "=r"((r)[15]), \
          "=r"((r)[16]), "=r"((r)[17]), "=r"((r)[18]), "=r"((r)[19]), \
          "=r"((r)[20]), "=r"((r)[21]), "=r"((r)[22]), "=r"((r)[23]), \
          "=r"((r)[24]), "=r"((r)[25]), "=r"((r)[26]), "=r"((r)[27]), \
          "=r"((r)[28]), "=r"((r)[29]), "=r"((r)[30]), "=r"((r)[31]) \
        : "r"(tmem_addr))

#define TCGEN05_ST_32X32B_X32(tmem_addr, r) \
    asm volatile( \
        "tcgen05.st.sync.aligned.32x32b.x32.b32 [%0], " \
        "{%1, %2, %3, %4, %5, %6, %7, %8, " \
        " %9, %10, %11, %12, %13, %14, %15, %16, " \
        " %17, %18, %19, %20, %21, %22, %23, %24, " \
        " %25, %26, %27, %28, %29, %30, %31, %32};" \
        :: "r"(tmem_addr), \
           "r"((r)[0]),  "r"((r)[1]),  "r"((r)[2]),  "r"((r)[3]), \
           "r"((r)[4]),  "r"((r)[5]),  "r"((r)[6]),  "r"((r)[7]), \
           "r"((r)[8]),  "r"((r)[9]),  "r"((r)[10]), "r"((r)[11]), \
           "r"((r)[12]), "r"((r)[13]), "r"((r)[14]), "r"((r)[15]), \
           "r"((r)[16]), "r"((r)[17]), "r"((r)[18]), "r"((r)[19]), \
           "r"((r)[20]), "r"((r)[21]), "r"((r)[22]), "r"((r)[23]), \
           "r"((r)[24]), "r"((r)[25]), "r"((r)[26]), "r"((r)[27]), \
           "r"((r)[28]), "r"((r)[29]), "r"((r)[30]), "r"((r)[31]) \
        : "memory")

// SW128 K-major descriptor: version=1, SBO=64, LBO=1
static constexpr uint64_t SMEM_DESC_BASE_SW128 =
    (uint64_t(2)  << 61) | (uint64_t(1) << 46) | (uint64_t(64) << 32) | (uint64_t(1) << 16);

__device__ __forceinline__ uint64_t make_desc(uint32_t addr) {
    return SMEM_DESC_BASE_SW128 | ((uint64_t)(addr >> 4) & 0x3FFF);
}

// TS-mode bf16 MMA: A in TMEM, B in SMEM
__device__ __forceinline__ void mma_f16_ts(uint32_t d_tmem, uint32_t a_tmem,
                                           uint64_t b_desc, uint32_t idesc, bool acc) {
    uint32_t en = acc ? 1u : 0u;
    asm volatile(
        "{\n\t.reg .pred p;\n\tsetp.ne.u32 p, %5, 0;\n\t"
        "tcgen05.mma.cta_group::1.kind::f16 [%0], [%1], %2, %3, {%4, %4, %4, %4}, p;\n\t}"
        :: "r"(d_tmem), "r"(a_tmem), "l"(b_desc), "r"(idesc), "r"(0u), "r"(en)
        : "memory");
}

// fp32 acc, bf16 a/b, M=128, N=64
static constexpr uint32_t MMA_IDESC =
    (1u << 4) | (1u << 7) | (1u << 10) | ((TN / 8) << 17) | ((TM / 16) << 24);

#endif  // HAS_TCGEN05

// ---------------------------------------------------------------------------
// SMEM layout (per CTA): 2 B buffers (32 KB), 4 tcol, 4 mbars
// ---------------------------------------------------------------------------
#define SMEM_B(b)     ((b) * 32768)
#define SMEM_TCOL(b)  (65536 + (b) * 256)
#define SMEM_MBAR(b)  (66560 + (b) * 8)
#define SMEM_TMEMPTR  66592
#define SMEM_TOTAL    66624

#define TMEM_COLS     256          // 2 x 64 D + 128 A
#define TMEM_D(b)     ((b) * 64)
#define TMEM_A_OFF    128

#define GRID_CTAS     296          // 2 CTAs per SM
#define NTHREADS      256

#if HAS_TCGEN05
// Load one 64-row x 256-col bf16 B tile into SW128 K-major blocked-atom
// layout (8 atom-rows; atom-col stride 8 KB). 128 threads.
__device__ __forceinline__ void load_tileB(char* smem, uint32_t dst,
                                           int gbase, int lt) {
    const uint4* src = reinterpret_cast<const uint4*>(g_featbf);
    #pragma unroll
    for (int k = 0; k < 16; ++k) {
        int idx = lt + k * 128;              // 0..2047
        int r = idx >> 5, ch = idx & 31;
        uint32_t byte = ((uint32_t)((r >> 3) + (ch >> 3) * 8) << 10)
                      + ((uint32_t)(r & 7) << 7) + ((uint32_t)(ch & 7) << 4);
        uint32_t sw = byte ^ ((byte >> 3) & 0x70);
        *reinterpret_cast<uint4*>(smem + dst + sw) =
            src[(size_t)(gbase + r) * 32 + ch];
    }
}

// Full-K (=256) TS MMA batch: 16 chained K=16 steps.
// B desc offset per step: atom-col stride 8192 B = 512 units, +2 units/step.
__device__ __forceinline__ void issue_mma_ts(uint32_t d_tmem, uint32_t a_tmem,
                                             uint32_t b_addr, uint32_t mbar) {
    uint64_t b_base = make_desc(b_addr);
    #pragma unroll
    for (int s = 0; s < 16; ++s) {
        uint64_t boff = ((uint64_t)(s >> 2) << 9) | (uint64_t)((s & 3) << 1);
        mma_f16_ts(d_tmem, a_tmem + s * 8, b_base + boff, MMA_IDESC, s > 0);
    }
    TCGEN05_COMMIT(mbar);
}
#endif

// ---------------------------------------------------------------------------
// Persistent sim kernel, 2 CTAs/SM. Per CTA: 256 threads.
//   warps 0-3: epilogue (rows w*32+lane, all 64 cols; 2x LDTM x32)
//   warps 4-7: loaders (B(t+2) + tcol(t+2), then elect-issue MMA(t+2))
// Named barrier 3 orders: epilogue's last LDTM(t) before MMA(t+2) writes D.
// ---------------------------------------------------------------------------
__global__ __launch_bounds__(NTHREADS, 2)
void sim_tc_kernel(float* out, int n, int d, int n_new, float alpha)
{
#if HAS_TCGEN05
    extern __shared__ __align__(1024) char smem[];
    const uint32_t sb = smem_u32(smem);
    const int tid  = threadIdx.x;
    const int wid  = tid >> 5;
    const int lane = tid & 31;

    if (wid == 0) {
        TCGEN05_ALLOC(sb + SMEM_TMEMPTR, TMEM_COLS);
        TCGEN05_RELINQUISH();
    }
    if (tid == 0) {
        MBARRIER_INIT(sb + SMEM_MBAR(0), 1);
        MBARRIER_INIT(sb + SMEM_MBAR(1), 1);
        MBARRIER_INIT(sb + SMEM_MBAR(2), 1);
        MBARRIER_INIT(sb + SMEM_MBAR(3), 1);
    }
    __syncthreads();

    uint32_t tmem;
    asm volatile("ld.shared.b32 %0, [%1];" : "=r"(tmem) : "r"(sb + SMEM_TMEMPTR));

    // ---- tile enumeration (TN=64 columns per tile) ---------------------------
    const int slabs_new = n_new / TM;            // 32
    const int cols_full = n / TN;                // 128
    const int cols_new  = n_new / TN;            // 64
    const int slabs_tot = n / TM;                // 64
    const int tiles_new = slabs_new * cols_full; // 4096
    const int tiles_tot = tiles_new + (slabs_tot - slabs_new) * cols_new; // 6144

    const int G = gridDim.x;
    int t   = (int)((long long)blockIdx.x       * tiles_tot / G);
    int end = (int)((long long)(blockIdx.x + 1) * tiles_tot / G);

    const bool is_loader = wid >= 4;
    const int  lt  = tid - 128;                  // loader-local tid
    const int  row = wid * 32 + lane;            // epilogue row (wid<4)

    int c = 0;                                   // global tile counter

    while (t < end) {
        // decode run: contiguous tiles sharing one row slab
        int slab, col0, slab_cols, slab_t0;
        if (t < tiles_new) {
            slab = t / cols_full; col0 = t - slab * cols_full;
            slab_cols = cols_full; slab_t0 = slab * cols_full;
        } else {
            int u = t - tiles_new;
            slab = slabs_new + u / cols_new; col0 = u % cols_new;
            slab_cols = cols_new;
            slab_t0 = tiles_new + (slab - slabs_new) * cols_new;
        }
        int run_len = slab_t0 + slab_cols - t;
        if (run_len > end - t) run_len = end - t;
        const int rowbase = slab * TM;
        const bool row_new = rowbase < n_new;
        const int kmax = run_len < 2 ? run_len : 2;

        // ---- run prologue ----------------------------------------------------
        // warps 0-3: A slab -> TMEM (row=tid, bf16x2 packed along K)
        // warps 4-7: B(c..c+kmax-1) + tcols
        if (!is_loader) {
            const uint4* src = reinterpret_cast<const uint4*>(g_featbf);
            const uint32_t woff = (uint32_t)wid << 21;
            #pragma unroll
            for (int q = 0; q < 4; ++q) {
                uint32_t regs[32];
                #pragma unroll
                for (int j = 0; j < 8; ++j) {
                    uint4 v = src[(size_t)(rowbase + tid) * 32 + q * 8 + j];
                    regs[j * 4 + 0] = v.x; regs[j * 4 + 1] = v.y;
                    regs[j * 4 + 2] = v.z; regs[j * 4 + 3] = v.w;
                }
                TCGEN05_ST_32X32B_X32(tmem + TMEM_A_OFF + q * 32 + woff, regs);
            }
            TCGEN05_WAIT_ST();
            TCGEN05_FENCE_BEFORE();
        } else {
            for (int k = 0; k < kmax; ++k) {
                const int cc0 = c + k;
                const int colbase = (col0 + k) * TN;
                load_tileB(smem, SMEM_B(cc0 & 1), colbase, lt);
                if (lt < TN)
                    ((int*)(smem + SMEM_TCOL(cc0 & 3)))[lt] = g_targ[colbase + lt];
            }
            asm volatile("fence.proxy.async.shared::cta;" ::: "memory");
        }
        __syncthreads();
        if (wid == 4 && elect_one()) {
            TCGEN05_FENCE_AFTER();
            for (int k = 0; k < kmax; ++k) {
                const int cc0 = c + k;
                issue_mma_ts(tmem + TMEM_D(cc0 & 1), tmem + TMEM_A_OFF,
                             sb + SMEM_B(cc0 & 1), sb + SMEM_MBAR(cc0 & 3));
            }
        }

        const int ti = __ldg(&g_targ[rowbase + row]);
        float p = 0.0f, ng = 0.0f;

        // ---- pipelined loop (MMA two tiles ahead) -----------------------------
        for (int i = 0; i < run_len; ++i) {
            const int cc = c + i;
            const bool has2 = (i + 2 < run_len);

            if (is_loader) {
                if (has2) {
                    const int cn = cc + 2;
                    const int colbase = (col0 + i + 2) * TN;
                    // B(cn&1)==B(cc&1): wait MMA(cc) done reading it
                    MBARRIER_WAIT_PARITY(sb + SMEM_MBAR(cc & 3), (cc >> 2) & 1);
                    load_tileB(smem, SMEM_B(cn & 1), colbase, lt);
                    if (lt < TN)
                        ((int*)(smem + SMEM_TCOL(cn & 3)))[lt] =
                            g_targ[colbase + lt];
                    asm volatile("fence.proxy.async.shared::cta;" ::: "memory");
                    // wait epilogue's LDTM(cc) done (D(cn&1)==D(cc&1))
                    asm volatile("bar.sync 3, 256;" ::: "memory");
                    if (wid == 4 && elect_one()) {
                        TCGEN05_FENCE_AFTER();
                        issue_mma_ts(tmem + TMEM_D(cn & 1), tmem + TMEM_A_OFF,
                                     sb + SMEM_B(cn & 1), sb + SMEM_MBAR(cn & 3));
                    }
                }
            } else {
                // epilogue(t): mbar fired >=1 window ago
                MBARRIER_WAIT_PARITY(sb + SMEM_MBAR(cc & 3), (cc >> 2) & 1);
                TCGEN05_FENCE_AFTER();

                const int colbase = (col0 + i) * TN;
                const bool do_pos = row_new && (colbase < n_new);
                const int* tc = (const int*)(smem + SMEM_TCOL(cc & 3));
                const uint32_t dbase = tmem + TMEM_D(cc & 1);
                uint32_t dr[32];

                // half 0
                TCGEN05_LD_32X32B_X32(dr, dbase);
                TCGEN05_WAIT_LD();
                if (do_pos) {
                    #pragma unroll
                    for (int j = 0; j < 32; ++j) {
                        const float s = __uint_as_float(dr[j]);
                        const int tj = tc[j];
                        if (ti != tj) { if (s > MARGIN) ng += s; }
                        else if (s < 1.0f - EPSV) p += 1.0f - s;
                    }
                } else {
                    #pragma unroll
                    for (int j = 0; j < 32; ++j) {
                        const float s = __uint_as_float(dr[j]);
                        if (ti != tc[j] && s > MARGIN) ng += s;
                    }
                }
                // half 1
                TCGEN05_LD_32X32B_X32(dr, dbase + 32);
                TCGEN05_WAIT_LD();
                if (has2)   // all D reads done -> release loaders' bar 3
                    asm volatile("bar.arrive 3, 256;" ::: "memory");
                if (do_pos) {
                    #pragma unroll
                    for (int j = 0; j < 32; ++j) {
                        const float s = __uint_as_float(dr[j]);
                        const int tj = tc[32 + j];
                        if (ti != tj) { if (s > MARGIN) ng += s; }
                        else if (s < 1.0f - EPSV) p += 1.0f - s;
                    }
                } else {
                    #pragma unroll
                    for (int j = 0; j < 32; ++j) {
                        const float s = __uint_as_float(dr[j]);
                        if (ti != tc[32 + j] && s > MARGIN) ng += s;
                    }
                }
            }

            __syncthreads();   // window boundary
        }

        // ---- run epilogue: flush accumulators (1 thread per row) -------------
        if (!is_loader) {
            atomicAdd(&g_neg[rowbase + row], ng);
            if (p != 0.0f) atomicAdd(&g_pos[rowbase + row], p);
        }

        c += run_len;
        t += run_len;
    }

    __syncthreads();
    if (wid == 0) TCGEN05_DEALLOC(tmem, TMEM_COLS);

    // ---- last CTA computes the final scalar ---------------------------------
    __threadfence();
    __shared__ int s_last;
    if (tid == 0)
        s_last = (atomicAdd(&g_done, 1) == gridDim.x - 1) ? 1 : 0;
    __syncthreads();
    if (s_last) {
        double* sh = reinterpret_cast<double*>(smem);
        const double a = (double)alpha;
        const double b = 1.0 - a;
        const double stale = (double)__ldcg(&g_pos[n_new - 1]);
        double s = 0.0;
        for (int i = tid; i < n; i += NTHREADS) {
            double pv = (i < n_new) ? (double)__ldcg(&g_pos[i]) : stale;
            s += a * pv + b * (double)__ldcg(&g_neg[i]);
        }
        sh[tid] = s;
        __syncthreads();
        for (int off = NTHREADS / 2; off > 0; off >>= 1) {
            if (tid < off) sh[tid] += sh[tid + off];
            __syncthreads();
        }
        if (tid == 0) out[0] = (float)(sh[0] / (double)n);
    }
#endif  // HAS_TCGEN05
}

// ---------------------------------------------------------------------------
extern "C" void kernel_launch(void* const* d_in, const int* in_sizes, int n_in,
                              void* d_out, int out_size)
{
    const float* feat = (const float*)d_in[0];
    const void*  targ = d_in[1];

    const int n     = in_sizes[1];             // 8192
    const int d     = in_sizes[0] / n;         // 256
    const int n_new = in_sizes[2];             // 4096
    const int n_old = (n_in > 3) ? in_sizes[3] : 0;
    const float alpha = (n_old != 0) ? 0.9f : 0.5f;

    cudaFuncSetAttribute(sim_tc_kernel,
                         cudaFuncAttributeMaxDynamicSharedMemorySize, SMEM_TOTAL);

    {
        int total4 = (n * d) >> 2;
        convert_kernel<<<(total4 + 255) / 256, 256>>>(feat, targ, n, d);
    }
    sim_tc_kernel<<<GRID_CTAS, NTHREADS, SMEM_TOTAL>>>((float*)d_out, n, d, n_new, alpha);
}